// round 1
// baseline (speedup 1.0000x reference)
#include <cuda_runtime.h>
#include <math.h>

#define S_LEN   2048
#define D_MODEL 1024
#define NHEADS  16
#define DKH     64
#define HALF_WIN 128
#define BQ      64
#define BKC     64
#define BATCH   2

// Scratch (static device globals: allocation-free per harness rules)
__device__ float g_q [BATCH * S_LEN * D_MODEL];
__device__ float g_k [BATCH * S_LEN * D_MODEL];
__device__ float g_v [BATCH * S_LEN * D_MODEL];
__device__ float g_ao[BATCH * S_LEN * D_MODEL];

// ---------------------------------------------------------------------------
// Y[M,N] = X[M,K] @ W[N,K]^T   (torch Linear).  128x128 tile, BK=8, 256 thr,
// 8x8 register microtile per thread. M%128==0, N%128==0, K%8==0 assumed.
// ---------------------------------------------------------------------------
__global__ __launch_bounds__(256) void sgemm_xwT(
    const float* __restrict__ X, const float* __restrict__ W,
    float* __restrict__ Y, int M, int N, int K)
{
    const int BM = 128, BN = 128, BK = 8;
    __shared__ float As[BK][BM];
    __shared__ float Bs[BK][BN];

    int bm = blockIdx.y * BM;
    int bn = blockIdx.x * BN;
    int tid = threadIdx.x;
    int ty = tid >> 4;        // 0..15
    int tx = tid & 15;        // 0..15
    int lr = tid >> 1;        // 0..127 (row to load)
    int lc = (tid & 1) * 4;   // 0 or 4 (float4 slot)

    const float* Xp = X + (size_t)(bm + lr) * K + lc;
    const float* Wp = W + (size_t)(bn + lr) * K + lc;

    float acc[8][8];
    #pragma unroll
    for (int i = 0; i < 8; i++)
        #pragma unroll
        for (int j = 0; j < 8; j++) acc[i][j] = 0.f;

    for (int k0 = 0; k0 < K; k0 += BK) {
        float4 av = *(const float4*)(Xp + k0);
        float4 bv = *(const float4*)(Wp + k0);
        As[lc + 0][lr] = av.x; As[lc + 1][lr] = av.y;
        As[lc + 2][lr] = av.z; As[lc + 3][lr] = av.w;
        Bs[lc + 0][lr] = bv.x; Bs[lc + 1][lr] = bv.y;
        Bs[lc + 2][lr] = bv.z; Bs[lc + 3][lr] = bv.w;
        __syncthreads();

        #pragma unroll
        for (int kk = 0; kk < BK; kk++) {
            float a[8], b[8];
            #pragma unroll
            for (int i = 0; i < 8; i++) a[i] = As[kk][ty * 8 + i];
            #pragma unroll
            for (int j = 0; j < 8; j++) b[j] = Bs[kk][tx * 8 + j];
            #pragma unroll
            for (int i = 0; i < 8; i++)
                #pragma unroll
                for (int j = 0; j < 8; j++)
                    acc[i][j] += a[i] * b[j];
        }
        __syncthreads();
    }

    #pragma unroll
    for (int i = 0; i < 8; i++) {
        float* yp = Y + (size_t)(bm + ty * 8 + i) * N + bn + tx * 8;
        float4 v0 = make_float4(acc[i][0], acc[i][1], acc[i][2], acc[i][3]);
        float4 v1 = make_float4(acc[i][4], acc[i][5], acc[i][6], acc[i][7]);
        *(float4*)(yp + 0) = v0;
        *(float4*)(yp + 4) = v1;
    }
}

// ---------------------------------------------------------------------------
// Windowed ALiBi flash attention. One block per (q-tile of 64, head, batch).
// 256 threads as 16x16 grid; each thread owns 4x4 of the score tile and 4x4
// of the output accumulator. Keys processed in aligned 64-chunks; online
// softmax stats in shared memory.
// ---------------------------------------------------------------------------
__global__ __launch_bounds__(256) void attn_win(
    const float* __restrict__ q, const float* __restrict__ k,
    const float* __restrict__ v, const float* __restrict__ slopes,
    float* __restrict__ o)
{
    extern __shared__ float sm[];
    float (*Qs)[DKH + 1] = (float (*)[DKH + 1]) sm;
    float (*Ks)[DKH + 1] = (float (*)[DKH + 1])(sm + 1 * BQ * (DKH + 1));
    float (*Vs)[DKH + 1] = (float (*)[DKH + 1])(sm + 2 * BQ * (DKH + 1));
    float (*Ss)[BKC + 1] = (float (*)[BKC + 1])(sm + 3 * BQ * (DKH + 1));
    __shared__ float m_s[BQ], l_s[BQ], alpha_s[BQ];

    int qt = blockIdx.x, h = blockIdx.y, b = blockIdx.z;
    int q0 = qt * BQ;
    int tid = threadIdx.x;
    int ty = tid >> 4, tx = tid & 15;
    float slope = slopes[h];

    // load Q tile, pre-scaled by 1/sqrt(dk) = 1/8
    for (int i = tid; i < BQ * DKH; i += 256) {
        int r = i >> 6, c = i & 63;
        Qs[r][c] = q[((size_t)b * S_LEN + q0 + r) * D_MODEL + h * DKH + c] * 0.125f;
    }
    if (tid < BQ) { m_s[tid] = -INFINITY; l_s[tid] = 0.f; }

    float acc[4][4];
    #pragma unroll
    for (int i = 0; i < 4; i++)
        #pragma unroll
        for (int j = 0; j < 4; j++) acc[i][j] = 0.f;

    int kstart = q0 - HALF_WIN; if (kstart < 0) kstart = 0;
    int kend   = q0 + BQ + HALF_WIN; if (kend > S_LEN) kend = S_LEN;
    // kstart/kend are multiples of 64 -> all chunks full, loads always valid

    for (int kc = kstart; kc < kend; kc += BKC) {
        __syncthreads();  // protect Ks/Vs/Ss reuse from previous iteration
        for (int i = tid; i < BKC * DKH; i += 256) {
            int r = i >> 6, c = i & 63;
            size_t base = ((size_t)b * S_LEN + kc + r) * D_MODEL + h * DKH + c;
            Ks[r][c] = k[base];
            Vs[r][c] = v[base];
        }
        __syncthreads();

        // S = Q @ K^T (this thread's 4x4)
        float sacc[4][4];
        #pragma unroll
        for (int i = 0; i < 4; i++)
            #pragma unroll
            for (int j = 0; j < 4; j++) sacc[i][j] = 0.f;

        #pragma unroll 8
        for (int kk = 0; kk < DKH; kk++) {
            float a0 = Qs[4 * ty + 0][kk], a1 = Qs[4 * ty + 1][kk];
            float a2 = Qs[4 * ty + 2][kk], a3 = Qs[4 * ty + 3][kk];
            float b0 = Ks[4 * tx + 0][kk], b1 = Ks[4 * tx + 1][kk];
            float b2 = Ks[4 * tx + 2][kk], b3 = Ks[4 * tx + 3][kk];
            sacc[0][0] += a0 * b0; sacc[0][1] += a0 * b1; sacc[0][2] += a0 * b2; sacc[0][3] += a0 * b3;
            sacc[1][0] += a1 * b0; sacc[1][1] += a1 * b1; sacc[1][2] += a1 * b2; sacc[1][3] += a1 * b3;
            sacc[2][0] += a2 * b0; sacc[2][1] += a2 * b1; sacc[2][2] += a2 * b2; sacc[2][3] += a2 * b3;
            sacc[3][0] += a3 * b0; sacc[3][1] += a3 * b1; sacc[3][2] += a3 * b2; sacc[3][3] += a3 * b3;
        }

        // ALiBi bias + window mask, stage scores to smem
        #pragma unroll
        for (int i = 0; i < 4; i++) {
            int qp = q0 + 4 * ty + i;
            #pragma unroll
            for (int j = 0; j < 4; j++) {
                int kp = kc + 4 * tx + j;
                int d = qp - kp;
                float sv = sacc[i][j] + slope * (float)d;
                if (d > HALF_WIN || d < -HALF_WIN) sv = -INFINITY;
                Ss[4 * ty + i][4 * tx + j] = sv;
            }
        }
        __syncthreads();

        // per-row online softmax update (one thread per row)
        if (tid < BQ) {
            float m_old = m_s[tid];
            float mx = m_old;
            #pragma unroll 8
            for (int j = 0; j < BKC; j++) mx = fmaxf(mx, Ss[tid][j]);
            float alpha, lsum = 0.f;
            if (mx == -INFINITY) {           // chunk fully masked for this row
                alpha = 1.f;
                #pragma unroll 8
                for (int j = 0; j < BKC; j++) Ss[tid][j] = 0.f;
            } else {
                alpha = __expf(m_old - mx);  // m_old=-inf -> 0 (acc is 0 anyway)
                #pragma unroll 8
                for (int j = 0; j < BKC; j++) {
                    float p = __expf(Ss[tid][j] - mx);  // -inf -> 0
                    Ss[tid][j] = p;
                    lsum += p;
                }
            }
            l_s[tid] = l_s[tid] * alpha + lsum;
            m_s[tid] = mx;
            alpha_s[tid] = alpha;
        }
        __syncthreads();

        // O = O*alpha + P @ V (this thread's 4 rows x 4 dk-cols)
        #pragma unroll
        for (int i = 0; i < 4; i++) {
            float al = alpha_s[4 * ty + i];
            #pragma unroll
            for (int j = 0; j < 4; j++) acc[i][j] *= al;
        }
        #pragma unroll 8
        for (int kk = 0; kk < BKC; kk++) {
            float p0 = Ss[4 * ty + 0][kk], p1 = Ss[4 * ty + 1][kk];
            float p2 = Ss[4 * ty + 2][kk], p3 = Ss[4 * ty + 3][kk];
            float v0 = Vs[kk][4 * tx + 0], v1 = Vs[kk][4 * tx + 1];
            float v2 = Vs[kk][4 * tx + 2], v3 = Vs[kk][4 * tx + 3];
            acc[0][0] += p0 * v0; acc[0][1] += p0 * v1; acc[0][2] += p0 * v2; acc[0][3] += p0 * v3;
            acc[1][0] += p1 * v0; acc[1][1] += p1 * v1; acc[1][2] += p1 * v2; acc[1][3] += p1 * v3;
            acc[2][0] += p2 * v0; acc[2][1] += p2 * v1; acc[2][2] += p2 * v2; acc[2][3] += p2 * v3;
            acc[3][0] += p3 * v0; acc[3][1] += p3 * v1; acc[3][2] += p3 * v2; acc[3][3] += p3 * v3;
        }
    }
    __syncthreads();

    #pragma unroll
    for (int i = 0; i < 4; i++) {
        int r = 4 * ty + i;
        float inv = 1.f / l_s[r];
        #pragma unroll
        for (int j = 0; j < 4; j++)
            o[((size_t)b * S_LEN + q0 + r) * D_MODEL + h * DKH + 4 * tx + j] =
                acc[i][j] * inv;
    }
}

// ---------------------------------------------------------------------------
extern "C" void kernel_launch(void* const* d_in, const int* in_sizes, int n_in,
                              void* d_out, int out_size)
{
    const float* x      = (const float*)d_in[0];
    const float* Wq     = (const float*)d_in[1];
    const float* Wk     = (const float*)d_in[2];
    const float* Wv     = (const float*)d_in[3];
    const float* Wo     = (const float*)d_in[4];
    const float* slopes = (const float*)d_in[5];
    float* out = (float*)d_out;

    float *qb, *kb, *vb, *aob;
    cudaGetSymbolAddress((void**)&qb,  g_q);
    cudaGetSymbolAddress((void**)&kb,  g_k);
    cudaGetSymbolAddress((void**)&vb,  g_v);
    cudaGetSymbolAddress((void**)&aob, g_ao);

    const int M = BATCH * S_LEN;   // 4096
    const int N = D_MODEL;         // 1024
    const int K = D_MODEL;         // 1024
    dim3 gg(N / 128, M / 128);

    sgemm_xwT<<<gg, 256>>>(x, Wq, qb, M, N, K);
    sgemm_xwT<<<gg, 256>>>(x, Wk, kb, M, N, K);
    sgemm_xwT<<<gg, 256>>>(x, Wv, vb, M, N, K);

    size_t smem = (size_t)4 * BQ * (DKH + 1) * sizeof(float);  // 66560 B
    cudaFuncSetAttribute(attn_win, cudaFuncAttributeMaxDynamicSharedMemorySize,
                         (int)smem);
    attn_win<<<dim3(S_LEN / BQ, NHEADS, BATCH), 256, smem>>>(qb, kb, vb, slopes, aob);

    sgemm_xwT<<<gg, 256>>>(aob, Wo, out, M, N, K);
}

// round 3
// speedup vs baseline: 1.9341x; 1.9341x over previous
#include <cuda_runtime.h>
#include <cuda_bf16.h>
#include <stdint.h>
#include <math.h>

#define S_LEN   2048
#define D_MODEL 1024
#define NHEADS  16
#define DKH     64
#define HALF_WIN 128
#define BQ      64
#define BKC     64
#define BATCH   2
#define MROWS   (BATCH * S_LEN)   // 4096
#define K3      (3 * D_MODEL)     // 3072
#define NQKV    3072

// ---------------- scratch (static device globals; no allocation) -----------
__device__ float g_qkv[MROWS * NQKV];                // fused q|k|v fp32
__device__ float g_ao [MROWS * D_MODEL];
__device__ __nv_bfloat16 g_xa  [MROWS * K3];         // x split [hi|lo|hi]
__device__ __nv_bfloat16 g_aoa [MROWS * K3];         // attn-out split
__device__ __nv_bfloat16 g_wqkv[NQKV * K3];          // [Wq;Wk;Wv] split [hi|hi|lo]
__device__ __nv_bfloat16 g_wo  [D_MODEL * K3];       // Wo split

// ---------------- fp32 -> bf16x3 split conversion ---------------------------
// modeB=0 (activations): blocks [hi | lo | hi]
// modeB=1 (weights):     blocks [hi | hi | lo]
// grid = number of rows; 256 thr/block, 4 floats/thread covers 1024 cols.
__global__ __launch_bounds__(256) void conv_split(
    const float* __restrict__ in, __nv_bfloat16* __restrict__ out, int modeB)
{
    int r = blockIdx.x;
    int c = threadIdx.x * 4;
    float4 v = *(const float4*)(in + (size_t)r * D_MODEL + c);
    float f[4] = {v.x, v.y, v.z, v.w};
    __nv_bfloat16 hi[4], lo[4];
    #pragma unroll
    for (int j = 0; j < 4; j++) {
        hi[j] = __float2bfloat16(f[j]);
        lo[j] = __float2bfloat16(f[j] - __bfloat162float(hi[j]));
    }
    __nv_bfloat162 hp0 = __halves2bfloat162(hi[0], hi[1]);
    __nv_bfloat162 hp1 = __halves2bfloat162(hi[2], hi[3]);
    __nv_bfloat162 lp0 = __halves2bfloat162(lo[0], lo[1]);
    __nv_bfloat162 lp1 = __halves2bfloat162(lo[2], lo[3]);
    __nv_bfloat162* o0 = (__nv_bfloat162*)(out + (size_t)r * K3 + c);
    __nv_bfloat162* o1 = (__nv_bfloat162*)(out + (size_t)r * K3 + D_MODEL + c);
    __nv_bfloat162* o2 = (__nv_bfloat162*)(out + (size_t)r * K3 + 2 * D_MODEL + c);
    o0[0] = hp0; o0[1] = hp1;
    if (modeB) { o1[0] = hp0; o1[1] = hp1; o2[0] = lp0; o2[1] = lp1; }
    else       { o1[0] = lp0; o1[1] = lp1; o2[0] = hp0; o2[1] = hp1; }
}

// ---------------- mma.sync bf16 GEMM: Y[M,N] = A[M,K3] @ B[N,K3]^T ----------
#define GBM 128
#define GBN 128
#define GBK 32
#define PADK 40                    // halves per smem row (32 + 8 pad)
#define STG 3
#define SMEM_GEMM (STG * (GBM + GBN) * PADK * 2)   // 61440 B

__device__ __forceinline__ uint32_t s2u(const void* p) {
    uint32_t a;
    asm("{ .reg .u64 t; cvta.to.shared.u64 t, %1; cvt.u32.u64 %0, t; }"
        : "=r"(a) : "l"(p));
    return a;
}
__device__ __forceinline__ void cp16(uint32_t dst, const void* src) {
    asm volatile("cp.async.cg.shared.global [%0], [%1], 16;" :: "r"(dst), "l"(src));
}

__global__ __launch_bounds__(256) void gemm_mma(
    const __nv_bfloat16* __restrict__ A,
    const __nv_bfloat16* __restrict__ B,
    float* __restrict__ Y, int N)
{
    extern __shared__ __nv_bfloat16 smem_g[];
    __nv_bfloat16 (*As)[GBM][PADK] = (__nv_bfloat16 (*)[GBM][PADK]) smem_g;
    __nv_bfloat16 (*Bs)[GBN][PADK] =
        (__nv_bfloat16 (*)[GBN][PADK])(smem_g + STG * GBM * PADK);

    int tid = threadIdx.x;
    int wid = tid >> 5, lane = tid & 31;
    int wm = wid & 1, wn = wid >> 1;            // 2x4 warp grid
    int bm = blockIdx.y * GBM, bn = blockIdx.x * GBN;
    int g = lane >> 2, tig = lane & 3;

    // loader mapping: idx -> (row, 16B chunk); 2 A chunks + 2 B chunks / thread
    int lrow = tid >> 2;                        // 0..63
    int lch  = tid & 3;                         // 0..3

    uint32_t as_base = s2u(&As[0][0][0]);
    uint32_t bs_base = s2u(&Bs[0][0][0]);

    const int NIT = K3 / GBK;                   // 96

#define LOAD_STAGE(s, k0)                                                     \
    do {                                                                      \
        _Pragma("unroll")                                                     \
        for (int i = 0; i < 2; i++) {                                         \
            int row = lrow + i * 64;                                          \
            cp16(as_base + ((uint32_t)(s) * GBM * PADK + row * PADK + lch * 8) * 2, \
                 A + (size_t)(bm + row) * K3 + (k0) + lch * 8);               \
            cp16(bs_base + ((uint32_t)(s) * GBN * PADK + row * PADK + lch * 8) * 2, \
                 B + (size_t)(bn + row) * K3 + (k0) + lch * 8);               \
        }                                                                     \
    } while (0)

    LOAD_STAGE(0, 0);
    asm volatile("cp.async.commit_group;");
    LOAD_STAGE(1, GBK);
    asm volatile("cp.async.commit_group;");

    float acc[4][4][4];
    #pragma unroll
    for (int i = 0; i < 4; i++)
        #pragma unroll
        for (int j = 0; j < 4; j++)
            #pragma unroll
            for (int t = 0; t < 4; t++) acc[i][j][t] = 0.f;

    for (int it = 0; it < NIT; it++) {
        int s = it % STG;
        asm volatile("cp.async.wait_group 1;");
        __syncthreads();

        #pragma unroll
        for (int kk = 0; kk < GBK; kk += 16) {
            uint32_t af[4][4], bf[4][2];
            #pragma unroll
            for (int i = 0; i < 4; i++) {
                int r = wm * 64 + i * 16 + g;
                af[i][0] = *(const uint32_t*)&As[s][r    ][kk + 2 * tig    ];
                af[i][1] = *(const uint32_t*)&As[s][r + 8][kk + 2 * tig    ];
                af[i][2] = *(const uint32_t*)&As[s][r    ][kk + 2 * tig + 8];
                af[i][3] = *(const uint32_t*)&As[s][r + 8][kk + 2 * tig + 8];
            }
            #pragma unroll
            for (int j = 0; j < 4; j++) {
                int n = wn * 32 + j * 8 + g;
                bf[j][0] = *(const uint32_t*)&Bs[s][n][kk + 2 * tig    ];
                bf[j][1] = *(const uint32_t*)&Bs[s][n][kk + 2 * tig + 8];
            }
            #pragma unroll
            for (int i = 0; i < 4; i++)
                #pragma unroll
                for (int j = 0; j < 4; j++)
                    asm volatile(
                        "mma.sync.aligned.m16n8k16.row.col.f32.bf16.bf16.f32 "
                        "{%0,%1,%2,%3}, {%4,%5,%6,%7}, {%8,%9}, {%0,%1,%2,%3};"
                        : "+f"(acc[i][j][0]), "+f"(acc[i][j][1]),
                          "+f"(acc[i][j][2]), "+f"(acc[i][j][3])
                        : "r"(af[i][0]), "r"(af[i][1]), "r"(af[i][2]), "r"(af[i][3]),
                          "r"(bf[j][0]), "r"(bf[j][1]));
        }

        if (it + 2 < NIT) LOAD_STAGE((it + 2) % STG, (it + 2) * GBK);
        asm volatile("cp.async.commit_group;");   // commit every iter (may be empty)
    }

    // epilogue: fp32 accumulators straight to global
    #pragma unroll
    for (int i = 0; i < 4; i++) {
        int r = bm + wm * 64 + i * 16 + g;
        #pragma unroll
        for (int j = 0; j < 4; j++) {
            int c = bn + wn * 32 + j * 8 + 2 * tig;
            *(float2*)&Y[(size_t)r * N + c]       = make_float2(acc[i][j][0], acc[i][j][1]);
            *(float2*)&Y[(size_t)(r + 8) * N + c] = make_float2(acc[i][j][2], acc[i][j][3]);
        }
    }
#undef LOAD_STAGE
}

// ---------------- windowed ALiBi flash attention (q/k/v strided in g_qkv) ---
__global__ __launch_bounds__(256) void attn_win(
    const float* __restrict__ q, const float* __restrict__ k,
    const float* __restrict__ v, const float* __restrict__ slopes,
    float* __restrict__ o)
{
    extern __shared__ float smf[];
    float (*Qs)[DKH + 1] = (float (*)[DKH + 1]) smf;
    float (*Ks)[DKH + 1] = (float (*)[DKH + 1])(smf + 1 * BQ * (DKH + 1));
    float (*Vs)[DKH + 1] = (float (*)[DKH + 1])(smf + 2 * BQ * (DKH + 1));
    float (*Ss)[BKC + 1] = (float (*)[BKC + 1])(smf + 3 * BQ * (DKH + 1));
    __shared__ float m_s[BQ], l_s[BQ], alpha_s[BQ];

    int qt = blockIdx.x, h = blockIdx.y, b = blockIdx.z;
    int q0 = qt * BQ;
    int tid = threadIdx.x;
    int ty = tid >> 4, tx = tid & 15;
    float slope = slopes[h];

    for (int i = tid; i < BQ * DKH; i += 256) {
        int r = i >> 6, c = i & 63;
        Qs[r][c] = q[((size_t)b * S_LEN + q0 + r) * NQKV + h * DKH + c] * 0.125f;
    }
    if (tid < BQ) { m_s[tid] = -INFINITY; l_s[tid] = 0.f; }

    float acc[4][4];
    #pragma unroll
    for (int i = 0; i < 4; i++)
        #pragma unroll
        for (int j = 0; j < 4; j++) acc[i][j] = 0.f;

    int kstart = q0 - HALF_WIN; if (kstart < 0) kstart = 0;
    int kend   = q0 + BQ + HALF_WIN; if (kend > S_LEN) kend = S_LEN;

    for (int kc = kstart; kc < kend; kc += BKC) {
        __syncthreads();
        for (int i = tid; i < BKC * DKH; i += 256) {
            int r = i >> 6, c = i & 63;
            size_t base = ((size_t)b * S_LEN + kc + r) * NQKV + h * DKH + c;
            Ks[r][c] = k[base];
            Vs[r][c] = v[base];
        }
        __syncthreads();

        float sacc[4][4];
        #pragma unroll
        for (int i = 0; i < 4; i++)
            #pragma unroll
            for (int j = 0; j < 4; j++) sacc[i][j] = 0.f;

        #pragma unroll 8
        for (int kk = 0; kk < DKH; kk++) {
            float a0 = Qs[4*ty+0][kk], a1 = Qs[4*ty+1][kk];
            float a2 = Qs[4*ty+2][kk], a3 = Qs[4*ty+3][kk];
            float b0 = Ks[4*tx+0][kk], b1 = Ks[4*tx+1][kk];
            float b2 = Ks[4*tx+2][kk], b3 = Ks[4*tx+3][kk];
            sacc[0][0] += a0*b0; sacc[0][1] += a0*b1; sacc[0][2] += a0*b2; sacc[0][3] += a0*b3;
            sacc[1][0] += a1*b0; sacc[1][1] += a1*b1; sacc[1][2] += a1*b2; sacc[1][3] += a1*b3;
            sacc[2][0] += a2*b0; sacc[2][1] += a2*b1; sacc[2][2] += a2*b2; sacc[2][3] += a2*b3;
            sacc[3][0] += a3*b0; sacc[3][1] += a3*b1; sacc[3][2] += a3*b2; sacc[3][3] += a3*b3;
        }

        #pragma unroll
        for (int i = 0; i < 4; i++) {
            int qp = q0 + 4*ty + i;
            #pragma unroll
            for (int j = 0; j < 4; j++) {
                int kp = kc + 4*tx + j;
                int d = qp - kp;
                float sv = sacc[i][j] + slope * (float)d;
                if (d > HALF_WIN || d < -HALF_WIN) sv = -INFINITY;
                Ss[4*ty+i][4*tx+j] = sv;
            }
        }
        __syncthreads();

        if (tid < BQ) {
            float m_old = m_s[tid];
            float mx = m_old;
            #pragma unroll 8
            for (int j = 0; j < BKC; j++) mx = fmaxf(mx, Ss[tid][j]);
            float alpha, lsum = 0.f;
            if (mx == -INFINITY) {
                alpha = 1.f;
                #pragma unroll 8
                for (int j = 0; j < BKC; j++) Ss[tid][j] = 0.f;
            } else {
                alpha = __expf(m_old - mx);
                #pragma unroll 8
                for (int j = 0; j < BKC; j++) {
                    float p = __expf(Ss[tid][j] - mx);
                    Ss[tid][j] = p;
                    lsum += p;
                }
            }
            l_s[tid] = l_s[tid] * alpha + lsum;
            m_s[tid] = mx;
            alpha_s[tid] = alpha;
        }
        __syncthreads();

        #pragma unroll
        for (int i = 0; i < 4; i++) {
            float al = alpha_s[4*ty+i];
            #pragma unroll
            for (int j = 0; j < 4; j++) acc[i][j] *= al;
        }
        #pragma unroll 8
        for (int kk = 0; kk < BKC; kk++) {
            float p0 = Ss[4*ty+0][kk], p1 = Ss[4*ty+1][kk];
            float p2 = Ss[4*ty+2][kk], p3 = Ss[4*ty+3][kk];
            float v0 = Vs[kk][4*tx+0], v1 = Vs[kk][4*tx+1];
            float v2 = Vs[kk][4*tx+2], v3 = Vs[kk][4*tx+3];
            acc[0][0] += p0*v0; acc[0][1] += p0*v1; acc[0][2] += p0*v2; acc[0][3] += p0*v3;
            acc[1][0] += p1*v0; acc[1][1] += p1*v1; acc[1][2] += p1*v2; acc[1][3] += p1*v3;
            acc[2][0] += p2*v0; acc[2][1] += p2*v1; acc[2][2] += p2*v2; acc[2][3] += p2*v3;
            acc[3][0] += p3*v0; acc[3][1] += p3*v1; acc[3][2] += p3*v2; acc[3][3] += p3*v3;
        }
    }
    __syncthreads();

    #pragma unroll
    for (int i = 0; i < 4; i++) {
        int r = 4*ty + i;
        float inv = 1.f / l_s[r];
        #pragma unroll
        for (int j = 0; j < 4; j++)
            o[((size_t)b * S_LEN + q0 + r) * D_MODEL + h * DKH + 4*tx + j] =
                acc[i][j] * inv;
    }
}

// ---------------------------------------------------------------------------
extern "C" void kernel_launch(void* const* d_in, const int* in_sizes, int n_in,
                              void* d_out, int out_size)
{
    const float* x      = (const float*)d_in[0];
    const float* Wq     = (const float*)d_in[1];
    const float* Wk     = (const float*)d_in[2];
    const float* Wv     = (const float*)d_in[3];
    const float* Wo     = (const float*)d_in[4];
    const float* slopes = (const float*)d_in[5];
    float* out = (float*)d_out;

    float *qkv, *aob;
    __nv_bfloat16 *xa, *aoa, *wqkv, *wo;
    cudaGetSymbolAddress((void**)&qkv,  g_qkv);
    cudaGetSymbolAddress((void**)&aob,  g_ao);
    cudaGetSymbolAddress((void**)&xa,   g_xa);
    cudaGetSymbolAddress((void**)&aoa,  g_aoa);
    cudaGetSymbolAddress((void**)&wqkv, g_wqkv);
    cudaGetSymbolAddress((void**)&wo,   g_wo);

    // splits
    conv_split<<<MROWS, 256>>>(x, xa, 0);
    conv_split<<<D_MODEL, 256>>>(Wq, wqkv + 0 * (size_t)D_MODEL * K3, 1);
    conv_split<<<D_MODEL, 256>>>(Wk, wqkv + 1 * (size_t)D_MODEL * K3, 1);
    conv_split<<<D_MODEL, 256>>>(Wv, wqkv + 2 * (size_t)D_MODEL * K3, 1);
    conv_split<<<D_MODEL, 256>>>(Wo, wo, 1);

    cudaFuncSetAttribute(gemm_mma, cudaFuncAttributeMaxDynamicSharedMemorySize,
                         SMEM_GEMM);

    // fused QKV projection: [4096 x 3072] = xa @ wqkv^T
    gemm_mma<<<dim3(NQKV / GBN, MROWS / GBM), 256, SMEM_GEMM>>>(xa, wqkv, qkv, NQKV);

    size_t smem = (size_t)4 * BQ * (DKH + 1) * sizeof(float);
    cudaFuncSetAttribute(attn_win, cudaFuncAttributeMaxDynamicSharedMemorySize,
                         (int)smem);
    attn_win<<<dim3(S_LEN / BQ, NHEADS, BATCH), 256, smem>>>(
        qkv, qkv + D_MODEL, qkv + 2 * D_MODEL, slopes, aob);

    conv_split<<<MROWS, 256>>>(aob, aoa, 0);

    // output projection: [4096 x 1024] = aoa @ wo^T
    gemm_mma<<<dim3(D_MODEL / GBN, MROWS / GBM), 256, SMEM_GEMM>>>(aoa, wo, out, D_MODEL);
}

// round 4
// speedup vs baseline: 2.1740x; 1.1240x over previous
#include <cuda_runtime.h>
#include <cuda_bf16.h>
#include <stdint.h>
#include <math.h>

#define S_LEN   2048
#define D_MODEL 1024
#define NHEADS  16
#define DKH     64
#define HALF_WIN 128
#define BQ      64
#define BKC     64
#define BATCH   2
#define MROWS   (BATCH * S_LEN)   // 4096
#define K3      (3 * D_MODEL)     // 3072
#define NQKV    3072

// ---------------- scratch (static device globals; no allocation) -----------
__device__ float g_qkv[MROWS * NQKV];                // fused q|k|v fp32
__device__ float g_ao [MROWS * D_MODEL];
__device__ __nv_bfloat16 g_xa  [MROWS * K3];         // x split [hi|lo|hi]
__device__ __nv_bfloat16 g_aoa [MROWS * K3];         // attn-out split
__device__ __nv_bfloat16 g_wqkv[NQKV * K3];          // [Wq;Wk;Wv] split [hi|hi|lo]
__device__ __nv_bfloat16 g_wo  [D_MODEL * K3];       // Wo split

// ---------------- fp32 -> bf16x3 split conversion ---------------------------
__global__ __launch_bounds__(256) void conv_split(
    const float* __restrict__ in, __nv_bfloat16* __restrict__ out, int modeB)
{
    int r = blockIdx.x;
    int c = threadIdx.x * 4;
    float4 v = *(const float4*)(in + (size_t)r * D_MODEL + c);
    float f[4] = {v.x, v.y, v.z, v.w};
    __nv_bfloat16 hi[4], lo[4];
    #pragma unroll
    for (int j = 0; j < 4; j++) {
        hi[j] = __float2bfloat16(f[j]);
        lo[j] = __float2bfloat16(f[j] - __bfloat162float(hi[j]));
    }
    __nv_bfloat162 hp0 = __halves2bfloat162(hi[0], hi[1]);
    __nv_bfloat162 hp1 = __halves2bfloat162(hi[2], hi[3]);
    __nv_bfloat162 lp0 = __halves2bfloat162(lo[0], lo[1]);
    __nv_bfloat162 lp1 = __halves2bfloat162(lo[2], lo[3]);
    __nv_bfloat162* o0 = (__nv_bfloat162*)(out + (size_t)r * K3 + c);
    __nv_bfloat162* o1 = (__nv_bfloat162*)(out + (size_t)r * K3 + D_MODEL + c);
    __nv_bfloat162* o2 = (__nv_bfloat162*)(out + (size_t)r * K3 + 2 * D_MODEL + c);
    o0[0] = hp0; o0[1] = hp1;
    if (modeB) { o1[0] = hp0; o1[1] = hp1; o2[0] = lp0; o2[1] = lp1; }
    else       { o1[0] = lp0; o1[1] = lp1; o2[0] = hp0; o2[1] = hp1; }
}

// ---------------- mma.sync bf16 GEMM: Y[M,N] = A[M,K3] @ B[N,K3]^T ----------
#define GBM 128
#define GBN 128
#define GBK 32
#define PADK 40                    // halves per smem row (32 + 8 pad)
#define STG 4
#define SMEM_GEMM (STG * (GBM + GBN) * PADK * 2)   // 81920 B

__device__ __forceinline__ uint32_t s2u(const void* p) {
    uint32_t a;
    asm("{ .reg .u64 t; cvta.to.shared.u64 t, %1; cvt.u32.u64 %0, t; }"
        : "=r"(a) : "l"(p));
    return a;
}
__device__ __forceinline__ void cp16(uint32_t dst, const void* src) {
    asm volatile("cp.async.cg.shared.global [%0], [%1], 16;" :: "r"(dst), "l"(src));
}
__device__ __forceinline__ void ldmx4(uint32_t& r0, uint32_t& r1, uint32_t& r2,
                                      uint32_t& r3, uint32_t addr) {
    asm volatile("ldmatrix.sync.aligned.m8n8.x4.shared.b16 {%0,%1,%2,%3}, [%4];"
                 : "=r"(r0), "=r"(r1), "=r"(r2), "=r"(r3) : "r"(addr));
}

__global__ __launch_bounds__(256, 2) void gemm_mma(
    const __nv_bfloat16* __restrict__ A,
    const __nv_bfloat16* __restrict__ B,
    float* __restrict__ Y, int N)
{
    extern __shared__ __nv_bfloat16 smem_g[];

    int tid = threadIdx.x;
    int wid = tid >> 5, lane = tid & 31;
    int wm = wid & 1, wn = wid >> 1;            // 2x4 warp grid
    int bm = blockIdx.y * GBM, bn = blockIdx.x * GBN;
    int g = lane >> 2, tig = lane & 3;

    int lrow = tid >> 2;                        // 0..63
    int lch  = tid & 3;                         // 0..3

    uint32_t as_base = s2u(smem_g);
    uint32_t bs_base = as_base + STG * GBM * PADK * 2;

    // ldmatrix base addresses (lane-dependent), byte offsets
    // A tiles: lanes 0-15 -> rows (lane&15), lanes 16-31 -> same rows, k+8
    uint32_t a_ld = as_base +
        ((uint32_t)(wm * 64 + (lane & 15)) * PADK + ((lane >> 4) * 8)) * 2;
    // B tiles: lane&7 row within 8-tile, bit3 -> k half, bit4 -> next n-tile
    uint32_t b_ld = bs_base +
        ((uint32_t)(wn * 32 + ((lane >> 4) * 8) + (lane & 7)) * PADK +
         (((lane >> 3) & 1) * 8)) * 2;

    const int NIT = K3 / GBK;                   // 96
    const uint32_t ASTG = GBM * PADK * 2;       // bytes per A stage
    const uint32_t BSTG = GBN * PADK * 2;

#define LOAD_STAGE(s, k0)                                                     \
    do {                                                                      \
        _Pragma("unroll")                                                     \
        for (int i = 0; i < 2; i++) {                                         \
            int row = lrow + i * 64;                                          \
            cp16(as_base + (uint32_t)(s) * ASTG + (row * PADK + lch * 8) * 2, \
                 A + (size_t)(bm + row) * K3 + (k0) + lch * 8);               \
            cp16(bs_base + (uint32_t)(s) * BSTG + (row * PADK + lch * 8) * 2, \
                 B + (size_t)(bn + row) * K3 + (k0) + lch * 8);               \
        }                                                                     \
    } while (0)

    LOAD_STAGE(0, 0);
    asm volatile("cp.async.commit_group;");
    LOAD_STAGE(1, GBK);
    asm volatile("cp.async.commit_group;");
    LOAD_STAGE(2, 2 * GBK);
    asm volatile("cp.async.commit_group;");

    float acc[4][4][4];
    #pragma unroll
    for (int i = 0; i < 4; i++)
        #pragma unroll
        for (int j = 0; j < 4; j++)
            #pragma unroll
            for (int t = 0; t < 4; t++) acc[i][j][t] = 0.f;

    for (int it = 0; it < NIT; it++) {
        int s = it & (STG - 1);
        asm volatile("cp.async.wait_group 2;");
        __syncthreads();

        uint32_t a_s = a_ld + s * ASTG;
        uint32_t b_s = b_ld + s * BSTG;

        #pragma unroll
        for (int kk = 0; kk < GBK; kk += 16) {
            uint32_t af[4][4], bf[4][2];
            #pragma unroll
            for (int i = 0; i < 4; i++)
                ldmx4(af[i][0], af[i][1], af[i][2], af[i][3],
                      a_s + (uint32_t)(i * 16 * PADK + kk) * 2);
            #pragma unroll
            for (int jp = 0; jp < 2; jp++)
                ldmx4(bf[2*jp][0], bf[2*jp][1], bf[2*jp+1][0], bf[2*jp+1][1],
                      b_s + (uint32_t)(jp * 16 * PADK + kk) * 2);
            #pragma unroll
            for (int i = 0; i < 4; i++)
                #pragma unroll
                for (int j = 0; j < 4; j++)
                    asm volatile(
                        "mma.sync.aligned.m16n8k16.row.col.f32.bf16.bf16.f32 "
                        "{%0,%1,%2,%3}, {%4,%5,%6,%7}, {%8,%9}, {%0,%1,%2,%3};"
                        : "+f"(acc[i][j][0]), "+f"(acc[i][j][1]),
                          "+f"(acc[i][j][2]), "+f"(acc[i][j][3])
                        : "r"(af[i][0]), "r"(af[i][1]), "r"(af[i][2]), "r"(af[i][3]),
                          "r"(bf[j][0]), "r"(bf[j][1]));
        }

        if (it + 3 < NIT) LOAD_STAGE((it + 3) & (STG - 1), (it + 3) * GBK);
        asm volatile("cp.async.commit_group;");
    }

    #pragma unroll
    for (int i = 0; i < 4; i++) {
        int r = bm + wm * 64 + i * 16 + g;
        #pragma unroll
        for (int j = 0; j < 4; j++) {
            int c = bn + wn * 32 + j * 8 + 2 * tig;
            *(float2*)&Y[(size_t)r * N + c]       = make_float2(acc[i][j][0], acc[i][j][1]);
            *(float2*)&Y[(size_t)(r + 8) * N + c] = make_float2(acc[i][j][2], acc[i][j][3]);
        }
    }
#undef LOAD_STAGE
}

// ---------------- windowed ALiBi flash attention (shuffle softmax) ---------
__global__ __launch_bounds__(256) void attn_win(
    const float* __restrict__ q, const float* __restrict__ k,
    const float* __restrict__ v, const float* __restrict__ slopes,
    float* __restrict__ o)
{
    extern __shared__ float smf[];
    float (*Qs)[DKH + 1] = (float (*)[DKH + 1]) smf;
    float (*Ks)[DKH + 1] = (float (*)[DKH + 1])(smf + 1 * BQ * (DKH + 1));
    float (*Vs)[DKH + 1] = (float (*)[DKH + 1])(smf + 2 * BQ * (DKH + 1));
    float (*Ss)[BKC + 1] = (float (*)[BKC + 1])(smf + 3 * BQ * (DKH + 1));

    int qt = blockIdx.x, h = blockIdx.y, b = blockIdx.z;
    int q0 = qt * BQ;
    int tid = threadIdx.x;
    int ty = tid >> 4, tx = tid & 15;
    float slope = slopes[h];

    for (int i = tid; i < BQ * DKH; i += 256) {
        int r = i >> 6, c = i & 63;
        Qs[r][c] = q[((size_t)b * S_LEN + q0 + r) * NQKV + h * DKH + c] * 0.125f;
    }

    float m_r[4], l_r[4];
    #pragma unroll
    for (int i = 0; i < 4; i++) { m_r[i] = -INFINITY; l_r[i] = 0.f; }

    float acc[4][4];
    #pragma unroll
    for (int i = 0; i < 4; i++)
        #pragma unroll
        for (int j = 0; j < 4; j++) acc[i][j] = 0.f;

    int kstart = q0 - HALF_WIN; if (kstart < 0) kstart = 0;
    int kend   = q0 + BQ + HALF_WIN; if (kend > S_LEN) kend = S_LEN;

    for (int kc = kstart; kc < kend; kc += BKC) {
        __syncthreads();  // previous iter done with Ks/Vs/Ss
        for (int i = tid; i < BKC * DKH; i += 256) {
            int r = i >> 6, c = i & 63;
            size_t base = ((size_t)b * S_LEN + kc + r) * NQKV + h * DKH + c;
            Ks[r][c] = k[base];
            Vs[r][c] = v[base];
        }
        __syncthreads();

        // S = Q @ K^T (4x4 per thread)
        float sacc[4][4];
        #pragma unroll
        for (int i = 0; i < 4; i++)
            #pragma unroll
            for (int j = 0; j < 4; j++) sacc[i][j] = 0.f;

        #pragma unroll 8
        for (int kk = 0; kk < DKH; kk++) {
            float a0 = Qs[4*ty+0][kk], a1 = Qs[4*ty+1][kk];
            float a2 = Qs[4*ty+2][kk], a3 = Qs[4*ty+3][kk];
            float b0 = Ks[4*tx+0][kk], b1 = Ks[4*tx+1][kk];
            float b2 = Ks[4*tx+2][kk], b3 = Ks[4*tx+3][kk];
            sacc[0][0] += a0*b0; sacc[0][1] += a0*b1; sacc[0][2] += a0*b2; sacc[0][3] += a0*b3;
            sacc[1][0] += a1*b0; sacc[1][1] += a1*b1; sacc[1][2] += a1*b2; sacc[1][3] += a1*b3;
            sacc[2][0] += a2*b0; sacc[2][1] += a2*b1; sacc[2][2] += a2*b2; sacc[2][3] += a2*b3;
            sacc[3][0] += a3*b0; sacc[3][1] += a3*b1; sacc[3][2] += a3*b2; sacc[3][3] += a3*b3;
        }

        // bias + mask
        #pragma unroll
        for (int i = 0; i < 4; i++) {
            int qp = q0 + 4*ty + i;
            #pragma unroll
            for (int j = 0; j < 4; j++) {
                int kp = kc + 4*tx + j;
                int d = qp - kp;
                float sv = sacc[i][j] + slope * (float)d;
                if (d > HALF_WIN || d < -HALF_WIN) sv = -INFINITY;
                sacc[i][j] = sv;
            }
        }

        // shuffle softmax over the 16 lanes sharing this ty (contiguous half-warp)
        #pragma unroll
        for (int i = 0; i < 4; i++) {
            float mx = fmaxf(fmaxf(sacc[i][0], sacc[i][1]),
                             fmaxf(sacc[i][2], sacc[i][3]));
            #pragma unroll
            for (int off = 8; off >= 1; off >>= 1)
                mx = fmaxf(mx, __shfl_xor_sync(0xffffffffu, mx, off));
            float mnew = fmaxf(m_r[i], mx);

            float alpha, lsum = 0.f;
            float p[4];
            if (mnew == -INFINITY) {     // fully masked so far
                alpha = 1.f;
                p[0] = p[1] = p[2] = p[3] = 0.f;
            } else {
                alpha = __expf(m_r[i] - mnew);    // m_r=-inf -> 0
                #pragma unroll
                for (int j = 0; j < 4; j++) {
                    p[j] = __expf(sacc[i][j] - mnew);   // -inf -> 0
                    lsum += p[j];
                }
            }
            #pragma unroll
            for (int off = 8; off >= 1; off >>= 1)
                lsum += __shfl_xor_sync(0xffffffffu, lsum, off);

            l_r[i] = l_r[i] * alpha + lsum;
            m_r[i] = mnew;
            #pragma unroll
            for (int j = 0; j < 4; j++) {
                Ss[4*ty+i][4*tx+j] = p[j];
                acc[i][j] *= alpha;
            }
        }
        __syncthreads();

        // O += P @ V
        #pragma unroll 8
        for (int kk = 0; kk < BKC; kk++) {
            float p0 = Ss[4*ty+0][kk], p1 = Ss[4*ty+1][kk];
            float p2 = Ss[4*ty+2][kk], p3 = Ss[4*ty+3][kk];
            float v0 = Vs[kk][4*tx+0], v1 = Vs[kk][4*tx+1];
            float v2 = Vs[kk][4*tx+2], v3 = Vs[kk][4*tx+3];
            acc[0][0] += p0*v0; acc[0][1] += p0*v1; acc[0][2] += p0*v2; acc[0][3] += p0*v3;
            acc[1][0] += p1*v0; acc[1][1] += p1*v1; acc[1][2] += p1*v2; acc[1][3] += p1*v3;
            acc[2][0] += p2*v0; acc[2][1] += p2*v1; acc[2][2] += p2*v2; acc[2][3] += p2*v3;
            acc[3][0] += p3*v0; acc[3][1] += p3*v1; acc[3][2] += p3*v2; acc[3][3] += p3*v3;
        }
    }

    #pragma unroll
    for (int i = 0; i < 4; i++) {
        int r = 4*ty + i;
        float inv = 1.f / l_r[i];
        #pragma unroll
        for (int j = 0; j < 4; j++)
            o[((size_t)b * S_LEN + q0 + r) * D_MODEL + h * DKH + 4*tx + j] =
                acc[i][j] * inv;
    }
}

// ---------------------------------------------------------------------------
extern "C" void kernel_launch(void* const* d_in, const int* in_sizes, int n_in,
                              void* d_out, int out_size)
{
    const float* x      = (const float*)d_in[0];
    const float* Wq     = (const float*)d_in[1];
    const float* Wk     = (const float*)d_in[2];
    const float* Wv     = (const float*)d_in[3];
    const float* Wo     = (const float*)d_in[4];
    const float* slopes = (const float*)d_in[5];
    float* out = (float*)d_out;

    float *qkv, *aob;
    __nv_bfloat16 *xa, *aoa, *wqkv, *wo;
    cudaGetSymbolAddress((void**)&qkv,  g_qkv);
    cudaGetSymbolAddress((void**)&aob,  g_ao);
    cudaGetSymbolAddress((void**)&xa,   g_xa);
    cudaGetSymbolAddress((void**)&aoa,  g_aoa);
    cudaGetSymbolAddress((void**)&wqkv, g_wqkv);
    cudaGetSymbolAddress((void**)&wo,   g_wo);

    conv_split<<<MROWS, 256>>>(x, xa, 0);
    conv_split<<<D_MODEL, 256>>>(Wq, wqkv + 0 * (size_t)D_MODEL * K3, 1);
    conv_split<<<D_MODEL, 256>>>(Wk, wqkv + 1 * (size_t)D_MODEL * K3, 1);
    conv_split<<<D_MODEL, 256>>>(Wv, wqkv + 2 * (size_t)D_MODEL * K3, 1);
    conv_split<<<D_MODEL, 256>>>(Wo, wo, 1);

    cudaFuncSetAttribute(gemm_mma, cudaFuncAttributeMaxDynamicSharedMemorySize,
                         SMEM_GEMM);

    gemm_mma<<<dim3(NQKV / GBN, MROWS / GBM), 256, SMEM_GEMM>>>(xa, wqkv, qkv, NQKV);

    size_t smem = (size_t)4 * BQ * (DKH + 1) * sizeof(float);
    cudaFuncSetAttribute(attn_win, cudaFuncAttributeMaxDynamicSharedMemorySize,
                         (int)smem);
    attn_win<<<dim3(S_LEN / BQ, NHEADS, BATCH), 256, smem>>>(
        qkv, qkv + D_MODEL, qkv + 2 * D_MODEL, slopes, aob);

    conv_split<<<MROWS, 256>>>(aob, aoa, 0);

    gemm_mma<<<dim3(D_MODEL / GBN, MROWS / GBM), 256, SMEM_GEMM>>>(aoa, wo, out, D_MODEL);
}